// round 1
// baseline (speedup 1.0000x reference)
#include <cuda_runtime.h>
#include <cstdint>
#include <cstddef>

// ---------------------------------------------------------------------------
// MSAColumnGlobalAttention — fp32, one CTA per residue column r.
// S=2048 (MSA depth), R=384 (residues), C_E=64, H=8, C_HID=8.
// ---------------------------------------------------------------------------

namespace {
constexpr int S_DIM = 2048;
constexpr int R_DIM = 384;
constexpr int CE    = 64;
constexpr int NTHR  = 256;
constexpr int RPT   = S_DIM / NTHR;   // 8 rows per thread

// shared memory layout (floats)
constexpr int OFF_KBUF = 0;                    // [8][2048]
constexpr int OFF_VBUF = OFF_KBUF + 8*S_DIM;   // [8][2048]
constexpr int OFF_MU   = OFF_VBUF + 8*S_DIM;   // [2048]
constexpr int OFF_RS   = OFF_MU   + S_DIM;     // [2048]
constexpr int OFF_MK   = OFF_RS   + S_DIM;     // [2048]
constexpr int OFF_WG   = OFF_MK   + S_DIM;     // [64][64]
constexpr int OFF_WO   = OFF_WG   + 4096;      // [64][64]
constexpr int OFF_WK   = OFF_WO   + 4096;      // [64][8]
constexpr int OFF_WV   = OFF_WK   + 512;       // [64][8]
constexpr int OFF_LNW  = OFF_WV   + 512;
constexpr int OFF_LNB  = OFF_LNW  + 64;
constexpr int OFF_BG   = OFF_LNB  + 64;
constexpr int OFF_BO   = OFF_BG   + 64;
constexpr int OFF_QVEC = OFF_BO   + 64;
constexpr int OFF_QH   = OFF_QVEC + 64;
constexpr int OFF_OSH  = OFF_QH   + 64;
constexpr int OFF_RED  = OFF_OSH  + 64;        // [8][72]
constexpr int OFF_MAX  = OFF_RED  + 8*72;      // [8]
constexpr int SMEM_FLOATS = OFF_MAX + 8;
constexpr size_t SMEM_BYTES = (size_t)SMEM_FLOATS * sizeof(float);
}

struct alignas(16) u64x2 { unsigned long long a, b; };

__device__ __forceinline__ unsigned long long pack2(float x) {
    unsigned long long r;
    asm("mov.b64 %0, {%1, %2};" : "=l"(r) : "f"(x), "f"(x));
    return r;
}
__device__ __forceinline__ float2 unpack2(unsigned long long v) {
    float2 f;
    asm("mov.b64 {%0, %1}, %2;" : "=f"(f.x), "=f"(f.y) : "l"(v));
    return f;
}
__device__ __forceinline__ void ffma2(unsigned long long& d,
                                      unsigned long long a,
                                      unsigned long long b) {
    asm("fma.rn.f32x2 %0, %1, %2, %0;" : "+l"(d) : "l"(a), "l"(b));
}

__global__ void __launch_bounds__(NTHR, 1)
msa_col_attn_kernel(const float* __restrict__ m,    const float* __restrict__ mask,
                    const float* __restrict__ ln_w, const float* __restrict__ ln_b,
                    const float* __restrict__ wq,   const float* __restrict__ wk,
                    const float* __restrict__ wv,   const float* __restrict__ wg,
                    const float* __restrict__ bg,   const float* __restrict__ wo,
                    const float* __restrict__ bo,   float* __restrict__ out)
{
    extern __shared__ float smf[];
    float* kbuf  = smf + OFF_KBUF;
    float* vbuf  = smf + OFF_VBUF;
    float* mu_s  = smf + OFF_MU;
    float* rs_s  = smf + OFF_RS;
    float* mk_s  = smf + OFF_MK;
    float* wg_s  = smf + OFF_WG;
    float* wo_s  = smf + OFF_WO;
    float* wk_s  = smf + OFF_WK;
    float* wv_s  = smf + OFF_WV;
    float* lnw_s = smf + OFF_LNW;
    float* lnb_s = smf + OFF_LNB;
    float* bg_s  = smf + OFF_BG;
    float* bo_s  = smf + OFF_BO;
    float* qvec_s= smf + OFF_QVEC;
    float* qh_s  = smf + OFF_QH;
    float* o_sh  = smf + OFF_OSH;
    float* red   = smf + OFF_RED;
    float* max_sh= smf + OFF_MAX;

    const int tid  = threadIdx.x;
    const int r    = blockIdx.x;
    const int lane = tid & 31;
    const int wid  = tid >> 5;

    // ---- load weights to shared ----
    for (int i = tid; i < 4096; i += NTHR) { wg_s[i] = wg[i]; wo_s[i] = wo[i]; }
    for (int i = tid; i < 512;  i += NTHR) { wk_s[i] = wk[i]; wv_s[i] = wv[i]; }
    if (tid < 64) {
        lnw_s[tid] = ln_w[tid]; lnb_s[tid] = ln_b[tid];
        bg_s[tid]  = bg[tid];   bo_s[tid]  = bo[tid];
    }
    __syncthreads();

    // =======================================================================
    // Phase A: LayerNorm, k/v projections, masked qsum
    // =======================================================================
    float qsum[CE];
    #pragma unroll
    for (int c = 0; c < CE; ++c) qsum[c] = 0.f;
    float msum = 0.f;

    #pragma unroll 1
    for (int i = 0; i < RPT; ++i) {
        const int s = tid + NTHR * i;
        const float* xr = m + ((size_t)s * R_DIM + r) * CE;
        float xs[CE];
        #pragma unroll
        for (int t = 0; t < 16; ++t) {
            float4 v = reinterpret_cast<const float4*>(xr)[t];
            xs[4*t+0] = v.x; xs[4*t+1] = v.y; xs[4*t+2] = v.z; xs[4*t+3] = v.w;
        }
        float sum = 0.f, sq = 0.f;
        #pragma unroll
        for (int c = 0; c < CE; ++c) { sum += xs[c]; sq = fmaf(xs[c], xs[c], sq); }
        const float muv  = sum * (1.f / CE);
        const float var  = sq * (1.f / CE) - muv * muv;
        const float rstd = rsqrtf(var + 1e-5f);
        const float mk   = mask[(size_t)s * R_DIM + r];
        mu_s[s] = muv; rs_s[s] = rstd; mk_s[s] = mk;
        msum += mk;

        unsigned long long ka[4], va[4];
        #pragma unroll
        for (int t = 0; t < 4; ++t) { ka[t] = 0ull; va[t] = 0ull; }

        #pragma unroll
        for (int c = 0; c < CE; ++c) {
            const float xn = (xs[c] - muv) * rstd * lnw_s[c] + lnb_s[c];
            qsum[c] = fmaf(xn, mk, qsum[c]);
            const unsigned long long xx = pack2(xn);
            const u64x2* wk2 = reinterpret_cast<const u64x2*>(wk_s + c * 8);
            const u64x2* wv2 = reinterpret_cast<const u64x2*>(wv_s + c * 8);
            u64x2 k0 = wk2[0], k1 = wk2[1];
            u64x2 v0 = wv2[0], v1 = wv2[1];
            ffma2(ka[0], xx, k0.a); ffma2(ka[1], xx, k0.b);
            ffma2(ka[2], xx, k1.a); ffma2(ka[3], xx, k1.b);
            ffma2(va[0], xx, v0.a); ffma2(va[1], xx, v0.b);
            ffma2(va[2], xx, v1.a); ffma2(va[3], xx, v1.b);
        }
        #pragma unroll
        for (int t = 0; t < 4; ++t) {
            float2 pk = unpack2(ka[t]);
            float2 pv = unpack2(va[t]);
            kbuf[(2*t+0)*S_DIM + s] = pk.x; kbuf[(2*t+1)*S_DIM + s] = pk.y;
            vbuf[(2*t+0)*S_DIM + s] = pv.x; vbuf[(2*t+1)*S_DIM + s] = pv.y;
        }
    }

    // ---- block reduce qsum / msum ----
    #pragma unroll
    for (int c = 0; c < CE; ++c) {
        #pragma unroll
        for (int o = 16; o > 0; o >>= 1)
            qsum[c] += __shfl_xor_sync(0xffffffffu, qsum[c], o);
    }
    #pragma unroll
    for (int o = 16; o > 0; o >>= 1)
        msum += __shfl_xor_sync(0xffffffffu, msum, o);

    if (lane == 0) {
        #pragma unroll
        for (int c = 0; c < CE; ++c) red[wid * 72 + c] = qsum[c];
        red[wid * 72 + 64] = msum;
    }
    __syncthreads();

    if (tid < 32) {
        float t0 = 0.f, t1 = 0.f, ms = 0.f;
        #pragma unroll
        for (int w = 0; w < 8; ++w) {
            t0 += red[w * 72 + tid];
            t1 += red[w * 72 + 32 + tid];
            ms += red[w * 72 + 64];
        }
        const float inv = __fdividef(1.f, ms + 1e-10f);
        qvec_s[tid]      = t0 * inv;
        qvec_s[tid + 32] = t1 * inv;
    }
    __syncthreads();

    // q-head projection: qh[o] = sum_c qvec[c]*wq[c][o] * C_HID^-0.5
    if (tid < 64) {
        float acc = 0.f;
        #pragma unroll 8
        for (int c = 0; c < CE; ++c) acc = fmaf(qvec_s[c], __ldg(wq + c * 64 + tid), acc);
        qh_s[tid] = acc * 0.3535533905932738f;
    }
    __syncthreads();

    // =======================================================================
    // Phase C: scores, softmax, o = softmax @ v
    // =======================================================================
    float sc[RPT][8];
    float mh[8];
    #pragma unroll
    for (int h = 0; h < 8; ++h) mh[h] = -1e30f;

    #pragma unroll
    for (int i = 0; i < RPT; ++i) {
        const int s = tid + NTHR * i;
        float kk[8];
        #pragma unroll
        for (int j = 0; j < 8; ++j) kk[j] = kbuf[j * S_DIM + s];
        const float bias = 1e9f * (mk_s[s] - 1.f);
        #pragma unroll
        for (int h = 0; h < 8; ++h) {
            float a = bias;
            #pragma unroll
            for (int j = 0; j < 8; ++j) a = fmaf(qh_s[h * 8 + j], kk[j], a);
            sc[i][h] = a;
            mh[h] = fmaxf(mh[h], a);
        }
    }
    #pragma unroll
    for (int h = 0; h < 8; ++h) {
        #pragma unroll
        for (int o = 16; o > 0; o >>= 1)
            mh[h] = fmaxf(mh[h], __shfl_xor_sync(0xffffffffu, mh[h], o));
    }
    if (lane == 0) {
        #pragma unroll
        for (int h = 0; h < 8; ++h) red[wid * 72 + h] = mh[h];
    }
    __syncthreads();
    if (tid < 8) {
        float mm = -1e30f;
        #pragma unroll
        for (int w = 0; w < 8; ++w) mm = fmaxf(mm, red[w * 72 + tid]);
        max_sh[tid] = mm;
    }
    __syncthreads();

    float gmax[8];
    #pragma unroll
    for (int h = 0; h < 8; ++h) gmax[h] = max_sh[h];

    float sumh[8];
    float oacc[64];
    #pragma unroll
    for (int h = 0; h < 8; ++h) sumh[h] = 0.f;
    #pragma unroll
    for (int c = 0; c < 64; ++c) oacc[c] = 0.f;

    #pragma unroll
    for (int i = 0; i < RPT; ++i) {
        const int s = tid + NTHR * i;
        float vv[8];
        #pragma unroll
        for (int j = 0; j < 8; ++j) vv[j] = vbuf[j * S_DIM + s];
        #pragma unroll
        for (int h = 0; h < 8; ++h) {
            const float e = __expf(sc[i][h] - gmax[h]);
            sumh[h] += e;
            #pragma unroll
            for (int j = 0; j < 8; ++j) oacc[h * 8 + j] = fmaf(e, vv[j], oacc[h * 8 + j]);
        }
    }
    #pragma unroll
    for (int c = 0; c < 64; ++c) {
        #pragma unroll
        for (int o = 16; o > 0; o >>= 1)
            oacc[c] += __shfl_xor_sync(0xffffffffu, oacc[c], o);
    }
    #pragma unroll
    for (int h = 0; h < 8; ++h) {
        #pragma unroll
        for (int o = 16; o > 0; o >>= 1)
            sumh[h] += __shfl_xor_sync(0xffffffffu, sumh[h], o);
    }
    if (lane == 0) {
        #pragma unroll
        for (int c = 0; c < 64; ++c) red[wid * 72 + c] = oacc[c];
        #pragma unroll
        for (int h = 0; h < 8; ++h)  red[wid * 72 + 64 + h] = sumh[h];
    }
    __syncthreads();
    if (tid < 64) {
        float t = 0.f, ss = 0.f;
        #pragma unroll
        for (int w = 0; w < 8; ++w) {
            t  += red[w * 72 + tid];
            ss += red[w * 72 + 64 + (tid >> 3)];
        }
        o_sh[tid] = __fdividef(t, ss);
    }
    __syncthreads();

    // =======================================================================
    // Phase D: gate + output projection (dominant cost, f32x2 packed)
    // =======================================================================
    #pragma unroll 1
    for (int i = 0; i < RPT; ++i) {
        const int s = tid + NTHR * i;
        const float* xrow = m + ((size_t)s * R_DIM + r) * CE;
        const float muv  = mu_s[s];
        const float rstd = rs_s[s];

        unsigned long long gacc[32];
        const unsigned long long* bg2 = reinterpret_cast<const unsigned long long*>(bg_s);
        #pragma unroll
        for (int t = 0; t < 32; ++t) gacc[t] = bg2[t];

        #pragma unroll 8
        for (int c = 0; c < CE; ++c) {
            const float xn = (__ldg(xrow + c) - muv) * rstd * lnw_s[c] + lnb_s[c];
            const unsigned long long xx = pack2(xn);
            const u64x2* w2 = reinterpret_cast<const u64x2*>(wg_s + c * 64);
            #pragma unroll
            for (int t = 0; t < 16; ++t) {
                u64x2 w = w2[t];
                ffma2(gacc[2*t+0], xx, w.a);
                ffma2(gacc[2*t+1], xx, w.b);
            }
        }

        float gg[64];   // (sigmoid(gate) * o_flat)[j] — local array
        #pragma unroll
        for (int t = 0; t < 32; ++t) {
            float2 p = unpack2(gacc[t]);
            const float e0 = __expf(-p.x);
            const float e1 = __expf(-p.y);
            gg[2*t+0] = o_sh[2*t+0] * __fdividef(1.f, 1.f + e0);
            gg[2*t+1] = o_sh[2*t+1] * __fdividef(1.f, 1.f + e1);
        }

        unsigned long long oa[32];
        const unsigned long long* bo2 = reinterpret_cast<const unsigned long long*>(bo_s);
        #pragma unroll
        for (int t = 0; t < 32; ++t) oa[t] = bo2[t];

        #pragma unroll 8
        for (int j = 0; j < CE; ++j) {
            const unsigned long long xx = pack2(gg[j]);
            const u64x2* w2 = reinterpret_cast<const u64x2*>(wo_s + j * 64);
            #pragma unroll
            for (int t = 0; t < 16; ++t) {
                u64x2 w = w2[t];
                ffma2(oa[2*t+0], xx, w.a);
                ffma2(oa[2*t+1], xx, w.b);
            }
        }

        float* orow = out + ((size_t)s * R_DIM + r) * CE;
        #pragma unroll
        for (int t = 0; t < 16; ++t) {
            float2 p0 = unpack2(oa[2*t+0]);
            float2 p1 = unpack2(oa[2*t+1]);
            float4 v; v.x = p0.x; v.y = p0.y; v.z = p1.x; v.w = p1.y;
            reinterpret_cast<float4*>(orow)[t] = v;
        }
    }
}

extern "C" void kernel_launch(void* const* d_in, const int* in_sizes, int n_in,
                              void* d_out, int out_size)
{
    (void)in_sizes; (void)n_in; (void)out_size;
    const float* m    = (const float*)d_in[0];
    const float* mask = (const float*)d_in[1];
    const float* ln_w = (const float*)d_in[2];
    const float* ln_b = (const float*)d_in[3];
    const float* wq   = (const float*)d_in[4];
    const float* wk   = (const float*)d_in[5];
    const float* wv   = (const float*)d_in[6];
    const float* wg   = (const float*)d_in[7];
    const float* bg   = (const float*)d_in[8];
    const float* wo   = (const float*)d_in[9];
    const float* bo   = (const float*)d_in[10];
    float* out = (float*)d_out;

    cudaFuncSetAttribute(msa_col_attn_kernel,
                         cudaFuncAttributeMaxDynamicSharedMemorySize,
                         (int)SMEM_BYTES);
    msa_col_attn_kernel<<<R_DIM, NTHR, SMEM_BYTES>>>(
        m, mask, ln_w, ln_b, wq, wk, wv, wg, bg, wo, bo, out);
}

// round 2
// speedup vs baseline: 1.0035x; 1.0035x over previous
#include <cuda_runtime.h>
#include <cstdint>
#include <cstddef>

// ---------------------------------------------------------------------------
// MSAColumnGlobalAttention — fp32, one CTA per residue column r.
// S=2048 (MSA depth), R=384 (residues), C_E=64, H=8, C_HID=8.
// ---------------------------------------------------------------------------

namespace {
constexpr int S_DIM = 2048;
constexpr int R_DIM = 384;
constexpr int CE    = 64;
constexpr int NTHR  = 256;
constexpr int RPT   = S_DIM / NTHR;   // 8 rows per thread

// shared memory layout (floats)
constexpr int OFF_KBUF = 0;                    // [8][2048]
constexpr int OFF_VBUF = OFF_KBUF + 8*S_DIM;   // [8][2048]
constexpr int OFF_MU   = OFF_VBUF + 8*S_DIM;   // [2048]
constexpr int OFF_RS   = OFF_MU   + S_DIM;     // [2048]
constexpr int OFF_MK   = OFF_RS   + S_DIM;     // [2048]
constexpr int OFF_WG   = OFF_MK   + S_DIM;     // [64][64]
constexpr int OFF_WO   = OFF_WG   + 4096;      // [64][64]
constexpr int OFF_WK   = OFF_WO   + 4096;      // [64][8]
constexpr int OFF_WV   = OFF_WK   + 512;       // [64][8]
constexpr int OFF_LNW  = OFF_WV   + 512;
constexpr int OFF_LNB  = OFF_LNW  + 64;
constexpr int OFF_BG   = OFF_LNB  + 64;
constexpr int OFF_BO   = OFF_BG   + 64;
constexpr int OFF_QVEC = OFF_BO   + 64;
constexpr int OFF_QH   = OFF_QVEC + 64;
constexpr int OFF_OSH  = OFF_QH   + 64;
constexpr int OFF_RED  = OFF_OSH  + 64;        // [8][72]
constexpr int OFF_MAX  = OFF_RED  + 8*72;      // [8]
constexpr int SMEM_FLOATS = OFF_MAX + 8;
constexpr size_t SMEM_BYTES = (size_t)SMEM_FLOATS * sizeof(float);
}

struct alignas(16) u64x2 { unsigned long long a, b; };

__device__ __forceinline__ unsigned long long pack2(float x) {
    unsigned long long r;
    asm("mov.b64 %0, {%1, %2};" : "=l"(r) : "f"(x), "f"(x));
    return r;
}
__device__ __forceinline__ float2 unpack2(unsigned long long v) {
    float2 f;
    asm("mov.b64 {%0, %1}, %2;" : "=f"(f.x), "=f"(f.y) : "l"(v));
    return f;
}
__device__ __forceinline__ void ffma2(unsigned long long& d,
                                      unsigned long long a,
                                      unsigned long long b) {
    asm("fma.rn.f32x2 %0, %1, %2, %0;" : "+l"(d) : "l"(a), "l"(b));
}

__global__ void __launch_bounds__(NTHR, 1)
msa_col_attn_kernel(const float* __restrict__ m,    const float* __restrict__ mask,
                    const float* __restrict__ ln_w, const float* __restrict__ ln_b,
                    const float* __restrict__ wq,   const float* __restrict__ wk,
                    const float* __restrict__ wv,   const float* __restrict__ wg,
                    const float* __restrict__ bg,   const float* __restrict__ wo,
                    const float* __restrict__ bo,   float* __restrict__ out)
{
    extern __shared__ float smf[];
    float* kbuf  = smf + OFF_KBUF;
    float* vbuf  = smf + OFF_VBUF;
    float* mu_s  = smf + OFF_MU;
    float* rs_s  = smf + OFF_RS;
    float* mk_s  = smf + OFF_MK;
    float* wg_s  = smf + OFF_WG;
    float* wo_s  = smf + OFF_WO;
    float* wk_s  = smf + OFF_WK;
    float* wv_s  = smf + OFF_WV;
    float* lnw_s = smf + OFF_LNW;
    float* lnb_s = smf + OFF_LNB;
    float* bg_s  = smf + OFF_BG;
    float* bo_s  = smf + OFF_BO;
    float* qvec_s= smf + OFF_QVEC;
    float* qh_s  = smf + OFF_QH;
    float* o_sh  = smf + OFF_OSH;
    float* red   = smf + OFF_RED;
    float* max_sh= smf + OFF_MAX;

    const int tid  = threadIdx.x;
    const int r    = blockIdx.x;
    const int lane = tid & 31;
    const int wid  = tid >> 5;

    // ---- load weights to shared ----
    for (int i = tid; i < 4096; i += NTHR) { wg_s[i] = wg[i]; wo_s[i] = wo[i]; }
    for (int i = tid; i < 512;  i += NTHR) { wk_s[i] = wk[i]; wv_s[i] = wv[i]; }
    if (tid < 64) {
        lnw_s[tid] = ln_w[tid]; lnb_s[tid] = ln_b[tid];
        bg_s[tid]  = bg[tid];   bo_s[tid]  = bo[tid];
    }
    __syncthreads();

    // =======================================================================
    // Phase A: LayerNorm, k/v projections, masked qsum
    // =======================================================================
    float qsum[CE];
    #pragma unroll
    for (int c = 0; c < CE; ++c) qsum[c] = 0.f;
    float msum = 0.f;

    #pragma unroll 1
    for (int i = 0; i < RPT; ++i) {
        const int s = tid + NTHR * i;
        const float* xr = m + ((size_t)s * R_DIM + r) * CE;
        float xs[CE];
        #pragma unroll
        for (int t = 0; t < 16; ++t) {
            float4 v = reinterpret_cast<const float4*>(xr)[t];
            xs[4*t+0] = v.x; xs[4*t+1] = v.y; xs[4*t+2] = v.z; xs[4*t+3] = v.w;
        }
        float sum = 0.f, sq = 0.f;
        #pragma unroll
        for (int c = 0; c < CE; ++c) { sum += xs[c]; sq = fmaf(xs[c], xs[c], sq); }
        const float muv  = sum * (1.f / CE);
        const float var  = sq * (1.f / CE) - muv * muv;
        const float rstd = rsqrtf(var + 1e-5f);
        const float mk   = mask[(size_t)s * R_DIM + r];
        mu_s[s] = muv; rs_s[s] = rstd; mk_s[s] = mk;
        msum += mk;

        unsigned long long ka[4], va[4];
        #pragma unroll
        for (int t = 0; t < 4; ++t) { ka[t] = 0ull; va[t] = 0ull; }

        #pragma unroll
        for (int c = 0; c < CE; ++c) {
            const float xn = (xs[c] - muv) * rstd * lnw_s[c] + lnb_s[c];
            qsum[c] = fmaf(xn, mk, qsum[c]);
            const unsigned long long xx = pack2(xn);
            const u64x2* wk2 = reinterpret_cast<const u64x2*>(wk_s + c * 8);
            const u64x2* wv2 = reinterpret_cast<const u64x2*>(wv_s + c * 8);
            u64x2 k0 = wk2[0], k1 = wk2[1];
            u64x2 v0 = wv2[0], v1 = wv2[1];
            ffma2(ka[0], xx, k0.a); ffma2(ka[1], xx, k0.b);
            ffma2(ka[2], xx, k1.a); ffma2(ka[3], xx, k1.b);
            ffma2(va[0], xx, v0.a); ffma2(va[1], xx, v0.b);
            ffma2(va[2], xx, v1.a); ffma2(va[3], xx, v1.b);
        }
        #pragma unroll
        for (int t = 0; t < 4; ++t) {
            float2 pk = unpack2(ka[t]);
            float2 pv = unpack2(va[t]);
            kbuf[(2*t+0)*S_DIM + s] = pk.x; kbuf[(2*t+1)*S_DIM + s] = pk.y;
            vbuf[(2*t+0)*S_DIM + s] = pv.x; vbuf[(2*t+1)*S_DIM + s] = pv.y;
        }
    }

    // ---- block reduce qsum / msum ----
    #pragma unroll
    for (int c = 0; c < CE; ++c) {
        #pragma unroll
        for (int o = 16; o > 0; o >>= 1)
            qsum[c] += __shfl_xor_sync(0xffffffffu, qsum[c], o);
    }
    #pragma unroll
    for (int o = 16; o > 0; o >>= 1)
        msum += __shfl_xor_sync(0xffffffffu, msum, o);

    if (lane == 0) {
        #pragma unroll
        for (int c = 0; c < CE; ++c) red[wid * 72 + c] = qsum[c];
        red[wid * 72 + 64] = msum;
    }
    __syncthreads();

    if (tid < 32) {
        float t0 = 0.f, t1 = 0.f, ms = 0.f;
        #pragma unroll
        for (int w = 0; w < 8; ++w) {
            t0 += red[w * 72 + tid];
            t1 += red[w * 72 + 32 + tid];
            ms += red[w * 72 + 64];
        }
        const float inv = __fdividef(1.f, ms + 1e-10f);
        qvec_s[tid]      = t0 * inv;
        qvec_s[tid + 32] = t1 * inv;
    }
    __syncthreads();

    // q-head projection: qh[o] = sum_c qvec[c]*wq[c][o] * C_HID^-0.5
    if (tid < 64) {
        float acc = 0.f;
        #pragma unroll 8
        for (int c = 0; c < CE; ++c) acc = fmaf(qvec_s[c], __ldg(wq + c * 64 + tid), acc);
        qh_s[tid] = acc * 0.3535533905932738f;
    }
    __syncthreads();

    // =======================================================================
    // Phase C: scores, softmax, o = softmax @ v
    // =======================================================================
    float sc[RPT][8];
    float mh[8];
    #pragma unroll
    for (int h = 0; h < 8; ++h) mh[h] = -1e30f;

    #pragma unroll
    for (int i = 0; i < RPT; ++i) {
        const int s = tid + NTHR * i;
        float kk[8];
        #pragma unroll
        for (int j = 0; j < 8; ++j) kk[j] = kbuf[j * S_DIM + s];
        const float bias = 1e9f * (mk_s[s] - 1.f);
        #pragma unroll
        for (int h = 0; h < 8; ++h) {
            float a = bias;
            #pragma unroll
            for (int j = 0; j < 8; ++j) a = fmaf(qh_s[h * 8 + j], kk[j], a);
            sc[i][h] = a;
            mh[h] = fmaxf(mh[h], a);
        }
    }
    #pragma unroll
    for (int h = 0; h < 8; ++h) {
        #pragma unroll
        for (int o = 16; o > 0; o >>= 1)
            mh[h] = fmaxf(mh[h], __shfl_xor_sync(0xffffffffu, mh[h], o));
    }
    if (lane == 0) {
        #pragma unroll
        for (int h = 0; h < 8; ++h) red[wid * 72 + h] = mh[h];
    }
    __syncthreads();
    if (tid < 8) {
        float mm = -1e30f;
        #pragma unroll
        for (int w = 0; w < 8; ++w) mm = fmaxf(mm, red[w * 72 + tid]);
        max_sh[tid] = mm;
    }
    __syncthreads();

    float gmax[8];
    #pragma unroll
    for (int h = 0; h < 8; ++h) gmax[h] = max_sh[h];

    float sumh[8];
    float oacc[64];
    #pragma unroll
    for (int h = 0; h < 8; ++h) sumh[h] = 0.f;
    #pragma unroll
    for (int c = 0; c < 64; ++c) oacc[c] = 0.f;

    #pragma unroll
    for (int i = 0; i < RPT; ++i) {
        const int s = tid + NTHR * i;
        float vv[8];
        #pragma unroll
        for (int j = 0; j < 8; ++j) vv[j] = vbuf[j * S_DIM + s];
        #pragma unroll
        for (int h = 0; h < 8; ++h) {
            const float e = __expf(sc[i][h] - gmax[h]);
            sumh[h] += e;
            #pragma unroll
            for (int j = 0; j < 8; ++j) oacc[h * 8 + j] = fmaf(e, vv[j], oacc[h * 8 + j]);
        }
    }
    #pragma unroll
    for (int c = 0; c < 64; ++c) {
        #pragma unroll
        for (int o = 16; o > 0; o >>= 1)
            oacc[c] += __shfl_xor_sync(0xffffffffu, oacc[c], o);
    }
    #pragma unroll
    for (int h = 0; h < 8; ++h) {
        #pragma unroll
        for (int o = 16; o > 0; o >>= 1)
            sumh[h] += __shfl_xor_sync(0xffffffffu, sumh[h], o);
    }
    if (lane == 0) {
        #pragma unroll
        for (int c = 0; c < 64; ++c) red[wid * 72 + c] = oacc[c];
        #pragma unroll
        for (int h = 0; h < 8; ++h)  red[wid * 72 + 64 + h] = sumh[h];
    }
    __syncthreads();
    if (tid < 64) {
        float t = 0.f, ss = 0.f;
        #pragma unroll
        for (int w = 0; w < 8; ++w) {
            t  += red[w * 72 + tid];
            ss += red[w * 72 + 64 + (tid >> 3)];
        }
        o_sh[tid] = __fdividef(t, ss);
    }
    __syncthreads();

    // =======================================================================
    // Phase D: gate + output projection (dominant cost, f32x2 packed)
    // =======================================================================
    #pragma unroll 1
    for (int i = 0; i < RPT; ++i) {
        const int s = tid + NTHR * i;
        const float* xrow = m + ((size_t)s * R_DIM + r) * CE;
        const float muv  = mu_s[s];
        const float rstd = rs_s[s];

        unsigned long long gacc[32];
        const unsigned long long* bg2 = reinterpret_cast<const unsigned long long*>(bg_s);
        #pragma unroll
        for (int t = 0; t < 32; ++t) gacc[t] = bg2[t];

        #pragma unroll 8
        for (int c = 0; c < CE; ++c) {
            const float xn = (__ldg(xrow + c) - muv) * rstd * lnw_s[c] + lnb_s[c];
            const unsigned long long xx = pack2(xn);
            const u64x2* w2 = reinterpret_cast<const u64x2*>(wg_s + c * 64);
            #pragma unroll
            for (int t = 0; t < 16; ++t) {
                u64x2 w = w2[t];
                ffma2(gacc[2*t+0], xx, w.a);
                ffma2(gacc[2*t+1], xx, w.b);
            }
        }

        float gg[64];   // (sigmoid(gate) * o_flat)[j] — local array
        #pragma unroll
        for (int t = 0; t < 32; ++t) {
            float2 p = unpack2(gacc[t]);
            const float e0 = __expf(-p.x);
            const float e1 = __expf(-p.y);
            gg[2*t+0] = o_sh[2*t+0] * __fdividef(1.f, 1.f + e0);
            gg[2*t+1] = o_sh[2*t+1] * __fdividef(1.f, 1.f + e1);
        }

        unsigned long long oa[32];
        const unsigned long long* bo2 = reinterpret_cast<const unsigned long long*>(bo_s);
        #pragma unroll
        for (int t = 0; t < 32; ++t) oa[t] = bo2[t];

        #pragma unroll 8
        for (int j = 0; j < CE; ++j) {
            const unsigned long long xx = pack2(gg[j]);
            const u64x2* w2 = reinterpret_cast<const u64x2*>(wo_s + j * 64);
            #pragma unroll
            for (int t = 0; t < 16; ++t) {
                u64x2 w = w2[t];
                ffma2(oa[2*t+0], xx, w.a);
                ffma2(oa[2*t+1], xx, w.b);
            }
        }

        float* orow = out + ((size_t)s * R_DIM + r) * CE;
        #pragma unroll
        for (int t = 0; t < 16; ++t) {
            float2 p0 = unpack2(oa[2*t+0]);
            float2 p1 = unpack2(oa[2*t+1]);
            float4 v; v.x = p0.x; v.y = p0.y; v.z = p1.x; v.w = p1.y;
            reinterpret_cast<float4*>(orow)[t] = v;
        }
    }
}

extern "C" void kernel_launch(void* const* d_in, const int* in_sizes, int n_in,
                              void* d_out, int out_size)
{
    (void)in_sizes; (void)n_in; (void)out_size;
    const float* m    = (const float*)d_in[0];
    const float* mask = (const float*)d_in[1];
    const float* ln_w = (const float*)d_in[2];
    const float* ln_b = (const float*)d_in[3];
    const float* wq   = (const float*)d_in[4];
    const float* wk   = (const float*)d_in[5];
    const float* wv   = (const float*)d_in[6];
    const float* wg   = (const float*)d_in[7];
    const float* bg   = (const float*)d_in[8];
    const float* wo   = (const float*)d_in[9];
    const float* bo   = (const float*)d_in[10];
    float* out = (float*)d_out;

    cudaFuncSetAttribute(msa_col_attn_kernel,
                         cudaFuncAttributeMaxDynamicSharedMemorySize,
                         (int)SMEM_BYTES);
    msa_col_attn_kernel<<<R_DIM, NTHR, SMEM_BYTES>>>(
        m, mask, ln_w, ln_b, wq, wk, wv, wg, bg, wo, bo, out);
}

// round 3
// speedup vs baseline: 1.2478x; 1.2435x over previous
#include <cuda_runtime.h>
#include <cstdint>
#include <cstddef>

namespace {
constexpr int S_DIM = 2048, R_DIM = 384, CE = 64;
constexpr int NTHR = 512, RPT = 4;          // phase A rows/thread
constexpr int CHUNK = 512, NCH = 4;         // phase D

// ---- shared layout (float offsets) ----
// union [0, 53248):
//   A/C: kbuf u64[4][2048] @u64 0, vbuf @u64 8192 (fl 0..32768)
//        scalars @ fl 33024: wk 512, wv 512, qvec 64, qh 64, red 16*72, max 8
//   D:   wg_u u64[64*80] @u64 0, wo_u @u64 5120 (fl 0..20480)
//        xnT fl[64*512] @ fl 20480..53248
constexpr int OFF_WK  = 33024, OFF_WV = 33536, OFF_QVEC = 34048, OFF_QH = 34112;
constexpr int OFF_RED = 34176, OFF_MAX = 35328;
constexpr int XNT_FL  = 20480;
constexpr int WD      = 80;                 // u64 stride per weight row
// persistent:
constexpr int OFF_MU  = 53248, OFF_RS = 55296, OFF_LNW = 57344, OFF_LNB = 57408;
constexpr int OFF_BGD = 57472, OFF_BOD = 57600, OFF_OSH = 57728;
constexpr int SMEM_FL = 57792;
constexpr size_t SMEM_BYTES = (size_t)SMEM_FL * 4;
}

struct alignas(16) u64x2 { unsigned long long a, b; };

__device__ __forceinline__ unsigned long long pack2(float x) {
    unsigned long long r;
    asm("mov.b64 %0, {%1, %2};" : "=l"(r) : "f"(x), "f"(x));
    return r;
}
__device__ __forceinline__ unsigned long long packAB(float a, float b) {
    unsigned long long r;
    asm("mov.b64 %0, {%1, %2};" : "=l"(r) : "f"(a), "f"(b));
    return r;
}
__device__ __forceinline__ float2 unpack2(unsigned long long v) {
    float2 f;
    asm("mov.b64 {%0, %1}, %2;" : "=f"(f.x), "=f"(f.y) : "l"(v));
    return f;
}
__device__ __forceinline__ void ffma2(unsigned long long& d,
                                      unsigned long long a, unsigned long long b) {
    asm("fma.rn.f32x2 %0, %1, %2, %0;" : "+l"(d) : "l"(a), "l"(b));
}
__device__ __forceinline__ unsigned long long addf2(unsigned long long a,
                                                    unsigned long long b) {
    unsigned long long r;
    asm("add.rn.f32x2 %0, %1, %2;" : "=l"(r) : "l"(a), "l"(b));
    return r;
}
__device__ __forceinline__ int swz(int c) { return (c >> 2) << 1; }

__global__ void __launch_bounds__(NTHR, 1)
msa_kernel(const float* __restrict__ m,    const float* __restrict__ mask,
           const float* __restrict__ ln_w, const float* __restrict__ ln_b,
           const float* __restrict__ wq,   const float* __restrict__ wk,
           const float* __restrict__ wv,   const float* __restrict__ wg,
           const float* __restrict__ bg,   const float* __restrict__ wo,
           const float* __restrict__ bo,   float* __restrict__ out)
{
    extern __shared__ float smf[];
    unsigned long long* kbuf_u = reinterpret_cast<unsigned long long*>(smf);
    unsigned long long* vbuf_u = kbuf_u + 4 * S_DIM;
    unsigned long long* wg_u   = reinterpret_cast<unsigned long long*>(smf);
    unsigned long long* wo_u   = wg_u + 64 * WD;
    float* xnT   = smf + XNT_FL;
    float* wk_s  = smf + OFF_WK;
    float* wv_s  = smf + OFF_WV;
    float* qvec_s= smf + OFF_QVEC;
    float* qh_s  = smf + OFF_QH;
    float* red   = smf + OFF_RED;
    float* max_sh= smf + OFF_MAX;
    float* mu_s  = smf + OFF_MU;
    float* rs_s  = smf + OFF_RS;
    float* lnw_s = smf + OFF_LNW;
    float* lnb_s = smf + OFF_LNB;
    unsigned long long* bgd = reinterpret_cast<unsigned long long*>(smf + OFF_BGD);
    unsigned long long* bod = reinterpret_cast<unsigned long long*>(smf + OFF_BOD);
    float* o_sh  = smf + OFF_OSH;

    const int tid  = threadIdx.x;
    const int r    = blockIdx.x;
    const int lane = tid & 31;
    const int wid  = tid >> 5;

    for (int i = tid; i < 512; i += NTHR) { wk_s[i] = wk[i]; wv_s[i] = wv[i]; }
    if (tid < 64) { lnw_s[tid] = ln_w[tid]; lnb_s[tid] = ln_b[tid]; }
    __syncthreads();

    // ============== Phase A: LN stats + k/v projections + masked qsum ======
    unsigned long long qsum2[32];
    #pragma unroll
    for (int t = 0; t < 32; ++t) qsum2[t] = 0ull;
    float msum = 0.f;

    #pragma unroll 1
    for (int i = 0; i < RPT; ++i) {
        const int s = tid + NTHR * i;
        const float4* xr = reinterpret_cast<const float4*>(m + ((size_t)s * R_DIM + r) * CE);
        float sum = 0.f, sq = 0.f;
        #pragma unroll
        for (int t = 0; t < 16; ++t) {
            float4 v = __ldg(xr + t);
            sum += v.x + v.y + v.z + v.w;
            sq = fmaf(v.x, v.x, sq); sq = fmaf(v.y, v.y, sq);
            sq = fmaf(v.z, v.z, sq); sq = fmaf(v.w, v.w, sq);
        }
        const float muv  = sum * (1.f / CE);
        const float var  = sq * (1.f / CE) - muv * muv;
        const float rstd = rsqrtf(var + 1e-5f);
        const float mk   = __ldg(mask + (size_t)s * R_DIM + r);
        mu_s[s] = muv; rs_s[s] = rstd; msum += mk;
        const unsigned long long mk2 = pack2(mk);

        unsigned long long ka[4], va[4];
        #pragma unroll
        for (int t = 0; t < 4; ++t) { ka[t] = 0ull; va[t] = 0ull; }

        #pragma unroll
        for (int t = 0; t < 16; ++t) {
            float4 v  = __ldg(xr + t);
            float4 lw = reinterpret_cast<const float4*>(lnw_s)[t];
            float4 lb = reinterpret_cast<const float4*>(lnb_s)[t];
            float xn0 = (v.x - muv) * rstd * lw.x + lb.x;
            float xn1 = (v.y - muv) * rstd * lw.y + lb.y;
            float xn2 = (v.z - muv) * rstd * lw.z + lb.z;
            float xn3 = (v.w - muv) * rstd * lw.w + lb.w;
            ffma2(qsum2[2*t],   packAB(xn0, xn1), mk2);
            ffma2(qsum2[2*t+1], packAB(xn2, xn3), mk2);
            const float xnv[4] = {xn0, xn1, xn2, xn3};
            #pragma unroll
            for (int j = 0; j < 4; ++j) {
                const int c = 4*t + j;
                const unsigned long long xx = pack2(xnv[j]);
                u64x2 k0 = reinterpret_cast<const u64x2*>(wk_s + c * 8)[0];
                u64x2 v0 = reinterpret_cast<const u64x2*>(wv_s + c * 8)[0];
                u64x2 k1 = reinterpret_cast<const u64x2*>(wk_s + c * 8)[1];
                u64x2 v1 = reinterpret_cast<const u64x2*>(wv_s + c * 8)[1];
                ffma2(ka[0], xx, k0.a); ffma2(ka[1], xx, k0.b);
                ffma2(ka[2], xx, k1.a); ffma2(ka[3], xx, k1.b);
                ffma2(va[0], xx, v0.a); ffma2(va[1], xx, v0.b);
                ffma2(va[2], xx, v1.a); ffma2(va[3], xx, v1.b);
            }
        }
        #pragma unroll
        for (int t = 0; t < 4; ++t) {
            kbuf_u[t * S_DIM + s] = ka[t];
            vbuf_u[t * S_DIM + s] = va[t];
        }
    }

    #pragma unroll
    for (int t = 0; t < 32; ++t) {
        #pragma unroll
        for (int o = 16; o > 0; o >>= 1)
            qsum2[t] = addf2(qsum2[t], __shfl_xor_sync(0xffffffffu, qsum2[t], o));
    }
    #pragma unroll
    for (int o = 16; o > 0; o >>= 1)
        msum += __shfl_xor_sync(0xffffffffu, msum, o);
    if (lane == 0) {
        #pragma unroll
        for (int t = 0; t < 32; ++t) {
            float2 p = unpack2(qsum2[t]);
            red[wid * 72 + 2*t] = p.x; red[wid * 72 + 2*t+1] = p.y;
        }
        red[wid * 72 + 64] = msum;
    }
    __syncthreads();

    if (tid < 64) {
        float t0 = 0.f, ms = 0.f;
        #pragma unroll
        for (int w = 0; w < 16; ++w) { t0 += red[w * 72 + tid]; ms += red[w * 72 + 64]; }
        qvec_s[tid] = t0 * __fdividef(1.f, ms + 1e-10f);
    }
    __syncthreads();
    if (tid < 64) {
        float acc = 0.f;
        #pragma unroll 8
        for (int c = 0; c < CE; ++c) acc = fmaf(qvec_s[c], __ldg(wq + c * 64 + tid), acc);
        qh_s[tid] = acc * 0.3535533905932738f;
    }
    __syncthreads();

    // ============== Phase C: scores / softmax / o ==========================
    {
        float sc[RPT][8], mh[8];
        #pragma unroll
        for (int h = 0; h < 8; ++h) mh[h] = -1e30f;

        #pragma unroll
        for (int i = 0; i < RPT; ++i) {
            const int s = tid + NTHR * i;
            unsigned long long kk[4];
            #pragma unroll
            for (int j = 0; j < 4; ++j) kk[j] = kbuf_u[j * S_DIM + s];
            const float bias = 1e9f * (__ldg(mask + (size_t)s * R_DIM + r) - 1.f);
            #pragma unroll
            for (int h = 0; h < 8; ++h) {
                unsigned long long acc = 0ull;
                #pragma unroll
                for (int j = 0; j < 4; ++j) {
                    unsigned long long q2 =
                        reinterpret_cast<const unsigned long long*>(qh_s)[h*4+j];
                    ffma2(acc, q2, kk[j]);
                }
                float2 p = unpack2(acc);
                float a = bias + p.x + p.y;
                sc[i][h] = a;
                mh[h] = fmaxf(mh[h], a);
            }
        }
        #pragma unroll
        for (int h = 0; h < 8; ++h) {
            #pragma unroll
            for (int o = 16; o > 0; o >>= 1)
                mh[h] = fmaxf(mh[h], __shfl_xor_sync(0xffffffffu, mh[h], o));
        }
        if (lane == 0) {
            #pragma unroll
            for (int h = 0; h < 8; ++h) red[wid * 72 + h] = mh[h];
        }
        __syncthreads();
        if (tid < 8) {
            float mm = -1e30f;
            #pragma unroll
            for (int w = 0; w < 16; ++w) mm = fmaxf(mm, red[w * 72 + tid]);
            max_sh[tid] = mm;
        }
        __syncthreads();

        // two head-halves to cap register pressure
        #pragma unroll 1
        for (int hb = 0; hb < 2; ++hb) {
            unsigned long long oacc2[16];
            float sumh[4];
            #pragma unroll
            for (int t = 0; t < 16; ++t) oacc2[t] = 0ull;
            #pragma unroll
            for (int h = 0; h < 4; ++h) sumh[h] = 0.f;

            #pragma unroll
            for (int i = 0; i < RPT; ++i) {
                const int s = tid + NTHR * i;
                unsigned long long vv[4];
                #pragma unroll
                for (int j = 0; j < 4; ++j) vv[j] = vbuf_u[j * S_DIM + s];
                #pragma unroll
                for (int h = 0; h < 4; ++h) {
                    const int hh = hb * 4 + h;
                    const float e = __expf(sc[i][hh] - max_sh[hh]);
                    sumh[h] += e;
                    const unsigned long long e2 = pack2(e);
                    #pragma unroll
                    for (int j = 0; j < 4; ++j) ffma2(oacc2[h*4+j], e2, vv[j]);
                }
            }
            #pragma unroll
            for (int t = 0; t < 16; ++t) {
                #pragma unroll
                for (int o = 16; o > 0; o >>= 1)
                    oacc2[t] = addf2(oacc2[t], __shfl_xor_sync(0xffffffffu, oacc2[t], o));
            }
            #pragma unroll
            for (int h = 0; h < 4; ++h) {
                #pragma unroll
                for (int o = 16; o > 0; o >>= 1)
                    sumh[h] += __shfl_xor_sync(0xffffffffu, sumh[h], o);
            }
            if (lane == 0) {
                #pragma unroll
                for (int t = 0; t < 16; ++t) {
                    float2 p = unpack2(oacc2[t]);
                    red[wid * 72 + hb*32 + 2*t]   = p.x;
                    red[wid * 72 + hb*32 + 2*t+1] = p.y;
                }
                #pragma unroll
                for (int h = 0; h < 4; ++h) red[wid * 72 + 64 + hb*4 + h] = sumh[h];
            }
            __syncthreads();
        }
        if (tid < 64) {
            float t0 = 0.f, ss = 0.f;
            #pragma unroll
            for (int w = 0; w < 16; ++w) {
                t0 += red[w * 72 + tid];
                ss += red[w * 72 + 64 + (tid >> 3)];
            }
            o_sh[tid] = __fdividef(t0, ss);
        }
        __syncthreads();
    }

    // ============== Phase D: gate GEMM + output GEMM =======================
    // duplicated-pair weight tables, 8 groups of (8 data + 2 pad) u64 per row
    for (int idx = tid; idx < 4096; idx += NTHR) {
        const int c = idx >> 6, col = idx & 63;
        const int dst = c * WD + (col >> 3) * 10 + (col & 7);
        wg_u[dst] = pack2(__ldg(wg + idx));
        wo_u[dst] = pack2(__ldg(wo + idx));
    }
    if (tid < 64) { bgd[tid] = pack2(__ldg(bg + tid)); bod[tid] = pack2(__ldg(bo + tid)); }
    __syncthreads();

    const int cg = tid & 7;
    const int rg = tid >> 3;
    const int R0 = rg * 8;

    #pragma unroll 1
    for (int ch = 0; ch < NCH; ++ch) {
        const int S0 = ch * CHUNK;

        // load + normalize into swizzled xnT (stride 512)
        #pragma unroll
        for (int k = 0; k < 16; ++k) {
            const int flat4 = tid + NTHR * k;
            const int row = flat4 >> 4;
            const int c4  = flat4 & 15;
            float4 v = __ldg(reinterpret_cast<const float4*>(
                         m + ((size_t)(S0 + row) * R_DIM + r) * CE) + c4);
            const float muv = mu_s[S0 + row];
            const float rsv = rs_s[S0 + row];
            float4 lw = reinterpret_cast<const float4*>(lnw_s)[c4];
            float4 lb = reinterpret_cast<const float4*>(lnb_s)[c4];
            const int c0 = c4 * 4;
            const int rw = row ^ (c4 * 2);     // swz(c0..c0+3) == 2*c4
            xnT[(c0+0) * 512 + rw] = (v.x - muv) * rsv * lw.x + lb.x;
            xnT[(c0+1) * 512 + rw] = (v.y - muv) * rsv * lw.y + lb.y;
            xnT[(c0+2) * 512 + rw] = (v.z - muv) * rsv * lw.z + lb.z;
            xnT[(c0+3) * 512 + rw] = (v.w - muv) * rsv * lw.w + lb.w;
        }
        __syncthreads();

        // GEMM1: gate = xn @ wg + bg
        unsigned long long acc[4][8];
        #pragma unroll
        for (int j = 0; j < 4; ++j)
            #pragma unroll
            for (int cc = 0; cc < 8; ++cc) acc[j][cc] = bgd[cg * 8 + cc];

        #pragma unroll 2
        for (int c = 0; c < CE; ++c) {
            const u64x2* wr = reinterpret_cast<const u64x2*>(wg_u + c * WD + cg * 10);
            u64x2 w0 = wr[0], w1 = wr[1], w2 = wr[2], w3 = wr[3];
            const float* xb = xnT + c * 512;
            const int sw = swz(c);
            unsigned long long xp[4];
            #pragma unroll
            for (int j = 0; j < 4; ++j)
                xp[j] = *reinterpret_cast<const unsigned long long*>(xb + ((R0 + 2*j) ^ sw));
            #pragma unroll
            for (int j = 0; j < 4; ++j) {
                ffma2(acc[j][0], xp[j], w0.a); ffma2(acc[j][1], xp[j], w0.b);
                ffma2(acc[j][2], xp[j], w1.a); ffma2(acc[j][3], xp[j], w1.b);
                ffma2(acc[j][4], xp[j], w2.a); ffma2(acc[j][5], xp[j], w2.b);
                ffma2(acc[j][6], xp[j], w3.a); ffma2(acc[j][7], xp[j], w3.b);
            }
        }
        __syncthreads();

        // sigmoid * o -> back into xnT (same transposed swizzled layout)
        #pragma unroll
        for (int cc = 0; cc < 8; ++cc) {
            const int col = cg * 8 + cc;
            const float osv = o_sh[col];
            float* gb = xnT + col * 512;
            const int sw = swz(col);
            #pragma unroll
            for (int j = 0; j < 4; ++j) {
                float2 p = unpack2(acc[j][cc]);
                const float g0 = osv * __fdividef(1.f, 1.f + __expf(-p.x));
                const float g1 = osv * __fdividef(1.f, 1.f + __expf(-p.y));
                *reinterpret_cast<unsigned long long*>(gb + ((R0 + 2*j) ^ sw)) =
                    packAB(g0, g1);
            }
        }
        __syncthreads();

        // GEMM2: out = gg @ wo + bo
        unsigned long long acc2[4][8];
        #pragma unroll
        for (int j = 0; j < 4; ++j)
            #pragma unroll
            for (int cc = 0; cc < 8; ++cc) acc2[j][cc] = bod[cg * 8 + cc];

        #pragma unroll 2
        for (int c = 0; c < CE; ++c) {
            const u64x2* wr = reinterpret_cast<const u64x2*>(wo_u + c * WD + cg * 10);
            u64x2 w0 = wr[0], w1 = wr[1], w2 = wr[2], w3 = wr[3];
            const float* xb = xnT + c * 512;
            const int sw = swz(c);
            unsigned long long xp[4];
            #pragma unroll
            for (int j = 0; j < 4; ++j)
                xp[j] = *reinterpret_cast<const unsigned long long*>(xb + ((R0 + 2*j) ^ sw));
            #pragma unroll
            for (int j = 0; j < 4; ++j) {
                ffma2(acc2[j][0], xp[j], w0.a); ffma2(acc2[j][1], xp[j], w0.b);
                ffma2(acc2[j][2], xp[j], w1.a); ffma2(acc2[j][3], xp[j], w1.b);
                ffma2(acc2[j][4], xp[j], w2.a); ffma2(acc2[j][5], xp[j], w2.b);
                ffma2(acc2[j][6], xp[j], w3.a); ffma2(acc2[j][7], xp[j], w3.b);
            }
        }

        #pragma unroll
        for (int j = 0; j < 4; ++j) {
            float lo[8], hi[8];
            #pragma unroll
            for (int cc = 0; cc < 8; ++cc) {
                float2 p = unpack2(acc2[j][cc]);
                lo[cc] = p.x; hi[cc] = p.y;
            }
            const int s0 = S0 + R0 + 2*j;
            float* o0 = out + ((size_t)s0 * R_DIM + r) * CE + cg * 8;
            float* o1 = o0 + (size_t)R_DIM * CE;
            reinterpret_cast<float4*>(o0)[0] = make_float4(lo[0], lo[1], lo[2], lo[3]);
            reinterpret_cast<float4*>(o0)[1] = make_float4(lo[4], lo[5], lo[6], lo[7]);
            reinterpret_cast<float4*>(o1)[0] = make_float4(hi[0], hi[1], hi[2], hi[3]);
            reinterpret_cast<float4*>(o1)[1] = make_float4(hi[4], hi[5], hi[6], hi[7]);
        }
        __syncthreads();
    }
}

extern "C" void kernel_launch(void* const* d_in, const int* in_sizes, int n_in,
                              void* d_out, int out_size)
{
    (void)in_sizes; (void)n_in; (void)out_size;
    cudaFuncSetAttribute(msa_kernel,
                         cudaFuncAttributeMaxDynamicSharedMemorySize, (int)SMEM_BYTES);
    msa_kernel<<<R_DIM, NTHR, SMEM_BYTES>>>(
        (const float*)d_in[0], (const float*)d_in[1], (const float*)d_in[2],
        (const float*)d_in[3], (const float*)d_in[4], (const float*)d_in[5],
        (const float*)d_in[6], (const float*)d_in[7], (const float*)d_in[8],
        (const float*)d_in[9], (const float*)d_in[10], (float*)d_out);
}